// round 1
// baseline (speedup 1.0000x reference)
#include <cuda_runtime.h>
#include <math.h>

// Problem constants
#define NSYS 4096      // tridiagonal system size (= NX)
#define NT   4096      // time steps
#define ROWP 4104      // padded row stride (multiple of 8 -> float4 aligned)
#define NTH  512       // threads in persistent kernel
#define ELEMS 8        // elements per thread (512*8 = 4096)

// Scratch / parameter globals (no cudaMalloc allowed)
__device__ float g_par[8];            // 0:dt 1:inv_dt 2:tscale(=4096/tmax) 3:aconst 4:r0
__device__ float g_cp[NSYS];
__device__ float g_den[NSYS];
__device__ float g_inlet[NT + 8];
__device__ float g_U[(size_t)(NT + 1) * ROWP];   // solution history, padded rows

// ---------------------------------------------------------------------------
// Kernel 1: reduce t_max, compute scalar params, Thomas factorization (fixed
// point converges geometrically -> 1024 sequential iters + constant fill),
// and the inlet table  inlet[n] = 1 + 0.5 sin(2*pi*n*dt).
// ---------------------------------------------------------------------------
__global__ void k_setup(const float* __restrict__ alpha,
                        const float* __restrict__ vel,
                        const float* __restrict__ r0p,
                        const float* __restrict__ r1p,
                        const float* __restrict__ tq, int nq) {
    __shared__ float smax[32];
    __shared__ float sbc[4];   // dt, cp_converged, den_converged
    int tid = threadIdx.x;
    int lane = tid & 31, wid = tid >> 5;

    float m = -1e30f;
    for (int i = tid; i < nq; i += blockDim.x) m = fmaxf(m, tq[i]);
    #pragma unroll
    for (int s = 16; s > 0; s >>= 1) m = fmaxf(m, __shfl_xor_sync(0xffffffffu, m, s));
    if (lane == 0) smax[wid] = m;
    __syncthreads();

    if (tid == 0) {
        float tmax = smax[0];
        int nw = (blockDim.x + 31) >> 5;
        for (int i = 1; i < nw; i++) tmax = fmaxf(tmax, smax[i]);
        float dt = tmax / 4096.0f;
        float inv_dt = 1.0f / dt;
        float al = *alpha, ve = *vel, r0 = *r0p, r1 = *r1p;
        float r_diff = al * 10000.0f;     // alpha / dx^2, dx = 0.01
        float r_adv  = ve * 50.0f;        // vel / (2 dx)
        float aconst = r_diff + r_adv;
        float b_int  = -2.0f * r_diff - inv_dt - r1;
        float c_int  = r_diff - r_adv;
        float b_last = -aconst - inv_dt - r1;
        g_par[0] = dt; g_par[1] = inv_dt; g_par[2] = 4096.0f / tmax;
        g_par[3] = aconst; g_par[4] = r0;
        // Thomas forward elimination (prefix until converged)
        g_cp[0] = 0.0f; g_den[0] = 1.0f;
        float cp = 0.0f;
        for (int i = 1; i < 1024; i++) {
            float den = b_int - aconst * cp;
            cp = c_int / den;
            g_den[i] = den; g_cp[i] = cp;
        }
        float denc = b_int - aconst * cp;
        sbc[0] = dt; sbc[1] = cp; sbc[2] = denc;
        g_den[NSYS - 1] = b_last - aconst * cp;   // last row has different b, c=0
        g_cp[NSYS - 1]  = 0.0f;
    }
    __syncthreads();
    float dt = sbc[0], cpc = sbc[1], denc = sbc[2];
    for (int i = 1024 + tid; i < NSYS - 1; i += blockDim.x) {
        g_den[i] = denc; g_cp[i] = cpc;
    }
    const float twopi = 6.283185307179586f;
    for (int n = tid; n <= NT; n += blockDim.x)
        g_inlet[n] = 1.0f + 0.5f * sinf(twopi * ((float)n * dt));
}

// ---------------------------------------------------------------------------
// Kernel 2: persistent single-CTA time loop. 512 threads x 8 contiguous
// elements. Per step: forward linrec (truncated Kogge-Stone, 3 shuffle
// rounds + one cross-warp hop), backward linrec (mirrored), store row.
// All scan multipliers are constants precomputed into registers; products
// beyond a 64-element window underflow to 0 (|av|,|cp| <= ~0.55), which is
// exactly the truncation that makes 3 rounds + 1 hop sufficient.
// ---------------------------------------------------------------------------
__global__ void __launch_bounds__(NTH, 1) k_main() {
    __shared__ float sF[16], sB[16];
    __shared__ float s_inlet[NT + 8];

    int tid = threadIdx.x;
    int lane = tid & 31, wid = tid >> 5;
    int e0 = tid * ELEMS;

    float inv_dt = g_par[1], aconst = g_par[3], r0 = g_par[4];

    float av[8], cv[8], f1[8], f0[8], Lf[8], Lb[8];
    #pragma unroll
    for (int k = 0; k < 8; k++) {
        int e = e0 + k;
        float den = g_den[e];
        float rc = 1.0f / den;
        av[k] = (e == 0) ? 0.0f : (-aconst * rc);
        cv[k] = -g_cp[e];
        f1[k] = -inv_dt * rc;
        f0[k] = r0 * (0.01f * (float)e) * rc;
    }
    Lf[0] = av[0];
    #pragma unroll
    for (int k = 1; k < 8; k++) Lf[k] = Lf[k - 1] * av[k];
    Lb[7] = cv[7];
    #pragma unroll
    for (int k = 6; k >= 0; k--) Lb[k] = cv[k] * Lb[k + 1];

    // ---- precompute warp-scan multipliers (constants across all steps) ----
    // Forward: rounds s=1,2,4. M_r[l] = prod of thread-A over lanes (l-2^r+1..l).
    float A = Lf[7];
    float Mf0 = (lane >= 1) ? A : 0.0f;
    float v = __shfl_up_sync(0xffffffffu, A, 1); if (lane >= 1) A *= v;
    float Mf1 = (lane >= 2) ? A : 0.0f;
    v = __shfl_up_sync(0xffffffffu, A, 2); if (lane >= 2) A *= v;
    float Mf2 = (lane >= 4) ? A : 0.0f;
    v = __shfl_up_sync(0xffffffffu, A, 4); if (lane >= 4) A *= v;
    v = __shfl_up_sync(0xffffffffu, A, 8); if (lane >= 8) A *= v;
    v = __shfl_up_sync(0xffffffffu, A, 16); if (lane >= 16) A *= v; // prod lanes 0..l
    float Qf = __shfl_up_sync(0xffffffffu, A, 1); if (lane == 0) Qf = 1.0f;

    // Backward (mirrored, shfl_down)
    float Bp = Lb[0];
    float Mb0 = (lane <= 30) ? Bp : 0.0f;
    v = __shfl_down_sync(0xffffffffu, Bp, 1); if (lane <= 30) Bp *= v;
    float Mb1 = (lane <= 29) ? Bp : 0.0f;
    v = __shfl_down_sync(0xffffffffu, Bp, 2); if (lane <= 29) Bp *= v;
    float Mb2 = (lane <= 27) ? Bp : 0.0f;
    v = __shfl_down_sync(0xffffffffu, Bp, 4); if (lane <= 27) Bp *= v;
    v = __shfl_down_sync(0xffffffffu, Bp, 8); if (lane <= 23) Bp *= v;
    v = __shfl_down_sync(0xffffffffu, Bp, 16); if (lane <= 15) Bp *= v; // prod l..31
    float Qb = __shfl_down_sync(0xffffffffu, Bp, 1); if (lane == 31) Qb = 1.0f;

    // inlet table into smem
    for (int i = tid; i <= NT; i += NTH) s_inlet[i] = g_inlet[i];

    // initial state u = 1, store row 0
    float u[8];
    #pragma unroll
    for (int k = 0; k < 8; k++) u[k] = 1.0f;
    {
        float4 one4 = make_float4(1.f, 1.f, 1.f, 1.f);
        float4* p = (float4*)(g_U + e0);
        p[0] = one4; p[1] = one4;
        if (tid == NTH - 1) g_U[NSYS] = 1.0f;
    }
    __syncthreads();

    float* row = g_U + ROWP + e0;
    float inl = s_inlet[1];
    for (int n = 0; n < NT; n++) {
        float inl_next = s_inlet[n + 2];   // one-past at n=NT-1: padded, unused

        // ---- forward sweep: dp_i = av_i dp_{i-1} + bv_i ----
        float m[8];
        float bv0 = fmaf(u[0], f1[0], f0[0]);
        if (tid == 0) bv0 = inl;
        m[0] = bv0;
        #pragma unroll
        for (int k = 1; k < 8; k++)
            m[k] = fmaf(av[k], m[k - 1], fmaf(u[k], f1[k], f0[k]));

        float P = m[7];
        v = __shfl_up_sync(0xffffffffu, P, 1); P = fmaf(Mf0, v, P);
        v = __shfl_up_sync(0xffffffffu, P, 2); P = fmaf(Mf1, v, P);
        v = __shfl_up_sync(0xffffffffu, P, 4); P = fmaf(Mf2, v, P);
        if (lane == 31) sF[wid] = P;
        float ex = __shfl_up_sync(0xffffffffu, P, 1); if (lane == 0) ex = 0.0f;
        __syncthreads();
        float C = (wid > 0) ? sF[wid - 1] : 0.0f;
        float cin = fmaf(Qf, C, ex);
        #pragma unroll
        for (int k = 0; k < 8; k++) m[k] = fmaf(Lf[k], cin, m[k]);   // m = dp

        // ---- backward sweep: x_i = cv_i x_{i+1} + dp_i ----
        #pragma unroll
        for (int k = 6; k >= 0; k--) m[k] = fmaf(cv[k], m[k + 1], m[k]); // local g
        float P2 = m[0];
        v = __shfl_down_sync(0xffffffffu, P2, 1); P2 = fmaf(Mb0, v, P2);
        v = __shfl_down_sync(0xffffffffu, P2, 2); P2 = fmaf(Mb1, v, P2);
        v = __shfl_down_sync(0xffffffffu, P2, 4); P2 = fmaf(Mb2, v, P2);
        if (lane == 0) sB[wid] = P2;
        float ex2 = __shfl_down_sync(0xffffffffu, P2, 1); if (lane == 31) ex2 = 0.0f;
        __syncthreads();
        float D = (wid < 15) ? sB[wid + 1] : 0.0f;
        float cin2 = fmaf(Qb, D, ex2);
        #pragma unroll
        for (int k = 0; k < 8; k++) u[k] = fmaf(Lb[k], cin2, m[k]);  // u = x

        // ---- store row n+1 ----
        float4* p = (float4*)row;
        p[0] = make_float4(u[0], u[1], u[2], u[3]);
        p[1] = make_float4(u[4], u[5], u[6], u[7]);
        if (tid == NTH - 1) row[NSYS - e0] = u[7];  // Neumann copy at outlet
        row += ROWP;
        inl = inl_next;
    }
}

// ---------------------------------------------------------------------------
// Kernel 3: time interpolation  out[b] = (1-w) U[idx0] + w U[idx1]
// ---------------------------------------------------------------------------
__global__ void k_interp(const float* __restrict__ tq, float* __restrict__ out) {
    int b = blockIdx.x;
    float tn = tq[b] * g_par[2];
    float f = floorf(tn);
    int i0 = (int)f;
    i0 = max(0, min(i0, NT - 1));
    float w = tn - (float)i0;
    const float* r0 = g_U + (size_t)i0 * ROWP;
    const float* r1 = r0 + ROWP;
    float* o = out + (size_t)b * (NSYS + 1);
    for (int x = threadIdx.x; x <= NSYS; x += blockDim.x)
        o[x] = (1.0f - w) * r0[x] + w * r1[x];
}

// ---------------------------------------------------------------------------
extern "C" void kernel_launch(void* const* d_in, const int* in_sizes, int n_in,
                              void* d_out, int out_size) {
    const float* alpha = (const float*)d_in[0];
    const float* vel   = (const float*)d_in[1];
    const float* r0    = (const float*)d_in[2];
    const float* r1    = (const float*)d_in[3];
    const float* t     = (const float*)d_in[4];
    int B = in_sizes[4];

    k_setup<<<1, 1024>>>(alpha, vel, r0, r1, t, B);
    k_main<<<1, NTH>>>();
    k_interp<<<B, 256>>>(t, (float*)d_out);
}